// round 1
// baseline (speedup 1.0000x reference)
#include <cuda_runtime.h>
#include <math.h>

// Problem constants
#define BSZ   8
#define TT    8          // time steps
#define HW    1024       // h*w
#define CK    256
#define CV    3
#define MEM   512
#define NPAIR 56         // 8 * 7
#define NTOT  1536       // HW + MEM
#define COEF_MEM 0.2f

// Logits scratch: 56 * 1024 * 1536 floats = 352 MB (static device array; no allocs)
__device__ float g_S[(size_t)NPAIR * HW * NTOT];

// ---------------------------------------------------------------------------
// Kernel 1: logits GEMM.  S[p][i][j] = sum_c Q[p][i][c] * B[p][j][c]
// Q[p] = k[b, t+1]  (1024 x 256)
// B[p] rows 0..1023   = k[b, t]      rows
// B[p] rows 1024..1535 = m_k[b, t]   rows
// NT GEMM (both operands K-contiguous), BM=BN=64, BK=16, 4x4 per thread.
// ---------------------------------------------------------------------------
#define GBM 64
#define GBN 64
#define GBK 16
#define GPAD 4

__global__ __launch_bounds__(256)
void gemm_logits_kernel(const float* __restrict__ kin,
                        const float* __restrict__ m_k)
{
    const int p  = blockIdx.z;          // pair 0..55
    const int bm = blockIdx.y;          // 0..15
    const int bn = blockIdx.x;          // 0..23
    const int b  = p / 7;
    const int t  = p % 7;

    const float* __restrict__ A =
        kin + ((size_t)(b * TT + t + 1) * HW + (size_t)bm * GBM) * CK;

    const int j0 = bn * GBN;
    const float* __restrict__ B;
    if (j0 < HW) {
        B = kin + ((size_t)(b * TT + t) * HW + (size_t)j0) * CK;
    } else {
        B = m_k + ((size_t)(b * TT + t) * MEM + (size_t)(j0 - HW)) * CK;
    }

    __shared__ __align__(16) float As[GBK][GBM + GPAD];
    __shared__ __align__(16) float Bs[GBK][GBN + GPAD];

    const int tid = threadIdx.x;        // 0..255
    const int tx  = tid & 15;           // 0..15  -> N micro
    const int ty  = tid >> 4;           // 0..15  -> M micro

    const int lr = tid >> 2;            // 0..63  loader row
    const int lk = (tid & 3) << 2;      // 0,4,8,12 loader k offset

    float acc00=0.f,acc01=0.f,acc02=0.f,acc03=0.f;
    float acc10=0.f,acc11=0.f,acc12=0.f,acc13=0.f;
    float acc20=0.f,acc21=0.f,acc22=0.f,acc23=0.f;
    float acc30=0.f,acc31=0.f,acc32=0.f,acc33=0.f;

    for (int kt = 0; kt < CK; kt += GBK) {
        float4 av = *(const float4*)(A + (size_t)lr * CK + kt + lk);
        float4 bv = *(const float4*)(B + (size_t)lr * CK + kt + lk);
        As[lk + 0][lr] = av.x; As[lk + 1][lr] = av.y;
        As[lk + 2][lr] = av.z; As[lk + 3][lr] = av.w;
        Bs[lk + 0][lr] = bv.x; Bs[lk + 1][lr] = bv.y;
        Bs[lk + 2][lr] = bv.z; Bs[lk + 3][lr] = bv.w;
        __syncthreads();

        #pragma unroll
        for (int kk = 0; kk < GBK; ++kk) {
            float4 a  = *(const float4*)(&As[kk][ty << 2]);
            float4 b4 = *(const float4*)(&Bs[kk][tx << 2]);
            acc00 = fmaf(a.x, b4.x, acc00);
            acc01 = fmaf(a.x, b4.y, acc01);
            acc02 = fmaf(a.x, b4.z, acc02);
            acc03 = fmaf(a.x, b4.w, acc03);
            acc10 = fmaf(a.y, b4.x, acc10);
            acc11 = fmaf(a.y, b4.y, acc11);
            acc12 = fmaf(a.y, b4.z, acc12);
            acc13 = fmaf(a.y, b4.w, acc13);
            acc20 = fmaf(a.z, b4.x, acc20);
            acc21 = fmaf(a.z, b4.y, acc21);
            acc22 = fmaf(a.z, b4.z, acc22);
            acc23 = fmaf(a.z, b4.w, acc23);
            acc30 = fmaf(a.w, b4.x, acc30);
            acc31 = fmaf(a.w, b4.y, acc31);
            acc32 = fmaf(a.w, b4.z, acc32);
            acc33 = fmaf(a.w, b4.w, acc33);
        }
        __syncthreads();
    }

    float* Sout = g_S + ((size_t)p * HW + (size_t)(bm * GBM + (ty << 2))) * NTOT
                      + j0 + (tx << 2);
    float4 r;
    r.x = acc00; r.y = acc01; r.z = acc02; r.w = acc03;
    *(float4*)(Sout + 0 * NTOT) = r;
    r.x = acc10; r.y = acc11; r.z = acc12; r.w = acc13;
    *(float4*)(Sout + 1 * NTOT) = r;
    r.x = acc20; r.y = acc21; r.z = acc22; r.w = acc23;
    *(float4*)(Sout + 2 * NTOT) = r;
    r.x = acc30; r.y = acc31; r.z = acc32; r.w = acc33;
    *(float4*)(Sout + 3 * NTOT) = r;
}

// ---------------------------------------------------------------------------
// Block reductions (256 threads = 8 warps)
// ---------------------------------------------------------------------------
__device__ __forceinline__ float block_reduce_max(float v, float* sh)
{
    const int lane = threadIdx.x & 31;
    const int wid  = threadIdx.x >> 5;
    #pragma unroll
    for (int o = 16; o; o >>= 1)
        v = fmaxf(v, __shfl_xor_sync(0xffffffffu, v, o));
    if (lane == 0) sh[wid] = v;
    __syncthreads();
    if (wid == 0) {
        float x = (lane < 8) ? sh[lane] : -INFINITY;
        #pragma unroll
        for (int o = 4; o; o >>= 1)
            x = fmaxf(x, __shfl_xor_sync(0xffffffffu, x, o));
        if (lane == 0) sh[0] = x;
    }
    __syncthreads();
    float r = sh[0];
    __syncthreads();
    return r;
}

__device__ __forceinline__ void block_reduce_sum4(float& s, float& a0,
                                                  float& a1, float& a2,
                                                  float* sh)
{
    const int lane = threadIdx.x & 31;
    const int wid  = threadIdx.x >> 5;
    #pragma unroll
    for (int o = 16; o; o >>= 1) {
        s  += __shfl_xor_sync(0xffffffffu, s,  o);
        a0 += __shfl_xor_sync(0xffffffffu, a0, o);
        a1 += __shfl_xor_sync(0xffffffffu, a1, o);
        a2 += __shfl_xor_sync(0xffffffffu, a2, o);
    }
    if (lane == 0) {
        sh[wid * 4 + 0] = s;  sh[wid * 4 + 1] = a0;
        sh[wid * 4 + 2] = a1; sh[wid * 4 + 3] = a2;
    }
    __syncthreads();
    if (wid == 0) {
        float x0 = (lane < 8) ? sh[lane * 4 + 0] : 0.f;
        float x1 = (lane < 8) ? sh[lane * 4 + 1] : 0.f;
        float x2 = (lane < 8) ? sh[lane * 4 + 2] : 0.f;
        float x3 = (lane < 8) ? sh[lane * 4 + 3] : 0.f;
        #pragma unroll
        for (int o = 4; o; o >>= 1) {
            x0 += __shfl_xor_sync(0xffffffffu, x0, o);
            x1 += __shfl_xor_sync(0xffffffffu, x1, o);
            x2 += __shfl_xor_sync(0xffffffffu, x2, o);
            x3 += __shfl_xor_sync(0xffffffffu, x3, o);
        }
        if (lane == 0) {
            sh[0] = x0; sh[1] = x1; sh[2] = x2; sh[3] = x3;
        }
    }
    __syncthreads();
    s  = sh[0]; a0 = sh[1]; a1 = sh[2]; a2 = sh[3];
    __syncthreads();
}

// ---------------------------------------------------------------------------
// Kernel 2: per-query dual softmax + weighted reconstruction.
// grid = (HW, NPAIR), block = 256
// ---------------------------------------------------------------------------
__global__ __launch_bounds__(256)
void softmax_recon_kernel(const float* __restrict__ v,
                          const float* __restrict__ m_v,
                          float* __restrict__ out)
{
    const int i = blockIdx.x;   // query 0..1023
    const int p = blockIdx.y;   // pair  0..55
    const int b = p / 7;
    const int t = p % 7;
    const int tid = threadIdx.x;

    __shared__ float sh[32];

    const float* __restrict__ srow = g_S + ((size_t)p * HW + i) * NTOT;
    const float* __restrict__ vsrc  = v   + (size_t)(b * TT + t) * HW  * CV;
    const float* __restrict__ mvsrc = m_v + (size_t)(b * TT + t) * MEM * CV;

    float res0 = 0.f, res1 = 0.f, res2 = 0.f;

    #pragma unroll
    for (int seg = 0; seg < 2; ++seg) {
        const int   len  = seg ? MEM : HW;
        const float* sp  = srow + (seg ? HW : 0);
        const float* vp  = seg ? mvsrc : vsrc;
        const float coef = seg ? COEF_MEM : (1.0f - COEF_MEM);

        float lm = -INFINITY;
        for (int j = tid; j < len; j += 256) lm = fmaxf(lm, sp[j]);
        const float smax = block_reduce_max(lm, sh);

        float s = 0.f, a0 = 0.f, a1 = 0.f, a2 = 0.f;
        for (int j = tid; j < len; j += 256) {
            float e = __expf(sp[j] - smax);
            const float* vr = vp + (size_t)j * CV;
            s  += e;
            a0 = fmaf(e, vr[0], a0);
            a1 = fmaf(e, vr[1], a1);
            a2 = fmaf(e, vr[2], a2);
        }
        block_reduce_sum4(s, a0, a1, a2, sh);
        const float inv = coef / s;
        res0 = fmaf(a0, inv, res0);
        res1 = fmaf(a1, inv, res1);
        res2 = fmaf(a2, inv, res2);
    }

    if (tid == 0) {
        float* o = out + ((size_t)p * HW + i) * CV;
        o[0] = res0; o[1] = res1; o[2] = res2;
    }
}

// ---------------------------------------------------------------------------
// Kernel 3: ground_truth = v[:, 1:]  -> second half of out
// total = 56*1024*3 = 172032 floats. For each b: contiguous chunk of 21504
// floats starting at v[(b*8+1)*1024*3].
// ---------------------------------------------------------------------------
__global__ __launch_bounds__(256)
void copy_gt_kernel(const float* __restrict__ v, float* __restrict__ out)
{
    const int total = NPAIR * HW * CV;                 // 172032
    int idx = blockIdx.x * blockDim.x + threadIdx.x;
    if (idx < total) {
        const int per_b = 7 * HW * CV;                 // 21504
        const int b = idx / per_b;
        const int r = idx - b * per_b;
        out[(size_t)total + idx] = v[(size_t)b * (TT * HW * CV) + (HW * CV) + r];
    }
}

// ---------------------------------------------------------------------------
extern "C" void kernel_launch(void* const* d_in, const int* in_sizes, int n_in,
                              void* d_out, int out_size)
{
    const float* k   = (const float*)d_in[0];
    const float* v   = (const float*)d_in[1];
    const float* m_k = (const float*)d_in[2];
    const float* m_v = (const float*)d_in[3];
    float* out = (float*)d_out;

    (void)in_sizes; (void)n_in; (void)out_size;

    dim3 ggrid(NTOT / GBN, HW / GBM, NPAIR);   // (24, 16, 56)
    gemm_logits_kernel<<<ggrid, 256>>>(k, m_k);

    dim3 sgrid(HW, NPAIR);                     // (1024, 56)
    softmax_recon_kernel<<<sgrid, 256>>>(v, m_v, out);

    const int total_gt = NPAIR * HW * CV;
    copy_gt_kernel<<<(total_gt + 255) / 256, 256>>>(v, out);
}

// round 2
// speedup vs baseline: 1.5758x; 1.5758x over previous
#include <cuda_runtime.h>
#include <math.h>

// Problem constants
#define BSZ   8
#define TT    8
#define HW    1024
#define CK    256
#define CV    3
#define MEM   512
#define NPAIR 56
#define NTOT  1536
#define COEF_MEM 0.2f

// Logits scratch: 56 * 1024 * 1536 floats = 352 MB
__device__ float g_S[(size_t)NPAIR * HW * NTOT];

// ---------------------------------------------------------------------------
// Kernel 1: logits GEMM (NT).  S[p][i][j] = sum_c Q[p][i][c] * B[p][j][c]
// BM=BN=128, BK=8, 256 threads, 8x8 microtile. 4 LDS.128 : 64 FFMA.
// ---------------------------------------------------------------------------
#define BM 128
#define BN 128
#define BK 8
#define SPAD 4
#define SW (BM + SPAD)   // 132 floats per k-plane

__global__ __launch_bounds__(256)
void gemm_logits_kernel(const float* __restrict__ kin,
                        const float* __restrict__ m_k)
{
    const int p  = blockIdx.z;          // pair 0..55
    const int bm = blockIdx.y;          // 0..7
    const int bn = blockIdx.x;          // 0..11
    const int b  = p / 7;
    const int t  = p % 7;

    const float* __restrict__ A =
        kin + ((size_t)(b * TT + t + 1) * HW + (size_t)bm * BM) * CK;

    const int j0 = bn * BN;
    const float* __restrict__ B;
    if (j0 < HW) {
        B = kin + ((size_t)(b * TT + t) * HW + (size_t)j0) * CK;
    } else {
        B = m_k + ((size_t)(b * TT + t) * MEM + (size_t)(j0 - HW)) * CK;
    }

    __shared__ __align__(16) float As[BK][SW];
    __shared__ __align__(16) float Bs[BK][SW];

    const int tid = threadIdx.x;        // 0..255
    const int tx  = tid & 15;           // N micro 0..15
    const int ty  = tid >> 4;           // M micro 0..15

    const int lr = tid >> 1;            // loader row 0..127
    const int lk = (tid & 1) << 2;      // 0 or 4

    const float* Aptr = A + (size_t)lr * CK + lk;
    const float* Bptr = B + (size_t)lr * CK + lk;

    float acc[8][8];
    #pragma unroll
    for (int i = 0; i < 8; ++i)
        #pragma unroll
        for (int j = 0; j < 8; ++j) acc[i][j] = 0.f;

    float4 an = *(const float4*)Aptr;
    float4 bn_ = *(const float4*)Bptr;

    for (int kt = 0; kt < CK; kt += BK) {
        As[lk + 0][lr] = an.x;  As[lk + 1][lr] = an.y;
        As[lk + 2][lr] = an.z;  As[lk + 3][lr] = an.w;
        Bs[lk + 0][lr] = bn_.x; Bs[lk + 1][lr] = bn_.y;
        Bs[lk + 2][lr] = bn_.z; Bs[lk + 3][lr] = bn_.w;
        __syncthreads();

        if (kt + BK < CK) {
            an  = *(const float4*)(Aptr + kt + BK);
            bn_ = *(const float4*)(Bptr + kt + BK);
        }

        #pragma unroll
        for (int kk = 0; kk < BK; ++kk) {
            float4 a0 = *(const float4*)(&As[kk][ty << 2]);
            float4 a1 = *(const float4*)(&As[kk][64 + (ty << 2)]);
            float4 b0 = *(const float4*)(&Bs[kk][tx << 2]);
            float4 b1 = *(const float4*)(&Bs[kk][64 + (tx << 2)]);
            float av[8] = {a0.x, a0.y, a0.z, a0.w, a1.x, a1.y, a1.z, a1.w};
            float bv[8] = {b0.x, b0.y, b0.z, b0.w, b1.x, b1.y, b1.z, b1.w};
            #pragma unroll
            for (int i = 0; i < 8; ++i)
                #pragma unroll
                for (int j = 0; j < 8; ++j)
                    acc[i][j] = fmaf(av[i], bv[j], acc[i][j]);
        }
        __syncthreads();
    }

    // Write 8x8 result: rows {ty*4+0..3, 64+ty*4+0..3}, cols {tx*4+0..3, 64+tx*4+0..3}
    const size_t rowbase = (size_t)p * HW + (size_t)bm * BM;
    #pragma unroll
    for (int ih = 0; ih < 2; ++ih) {
        #pragma unroll
        for (int i = 0; i < 4; ++i) {
            const int m = ih * 64 + (ty << 2) + i;
            float* Sout = g_S + (rowbase + m) * NTOT + j0;
            float4 r0, r1;
            r0.x = acc[ih * 4 + i][0]; r0.y = acc[ih * 4 + i][1];
            r0.z = acc[ih * 4 + i][2]; r0.w = acc[ih * 4 + i][3];
            r1.x = acc[ih * 4 + i][4]; r1.y = acc[ih * 4 + i][5];
            r1.z = acc[ih * 4 + i][6]; r1.w = acc[ih * 4 + i][7];
            *(float4*)(Sout + (tx << 2))      = r0;
            *(float4*)(Sout + 64 + (tx << 2)) = r1;
        }
    }
}

// ---------------------------------------------------------------------------
// Kernel 2: warp-per-row dual softmax + reconstruction.
// block = 256 (8 warps), grid = NPAIR*HW/8 = 7168
// ---------------------------------------------------------------------------
__global__ __launch_bounds__(256)
void softmax_recon_kernel(const float* __restrict__ v,
                          const float* __restrict__ m_v,
                          float* __restrict__ out)
{
    const int lane = threadIdx.x & 31;
    const int row  = blockIdx.x * 8 + (threadIdx.x >> 5);   // 0..57343
    const int p = row >> 10;          // pair
    const int i = row & 1023;         // query
    const int b = p / 7;
    const int t = p % 7;

    const float* __restrict__ srow = g_S + ((size_t)p * HW + i) * NTOT;
    const float* __restrict__ vsrc  = v   + (size_t)(b * TT + t) * HW  * CV;
    const float* __restrict__ mvsrc = m_v + (size_t)(b * TT + t) * MEM * CV;

    float res0 = 0.f, res1 = 0.f, res2 = 0.f;

    #pragma unroll
    for (int seg = 0; seg < 2; ++seg) {
        const int   len  = seg ? MEM : HW;
        const float* sp  = srow + (seg ? HW : 0);
        const float* vp  = seg ? mvsrc : vsrc;
        const float coef = seg ? COEF_MEM : (1.0f - COEF_MEM);

        float lm = -INFINITY;
        for (int j = lane; j < len; j += 32) lm = fmaxf(lm, sp[j]);
        #pragma unroll
        for (int o = 16; o; o >>= 1)
            lm = fmaxf(lm, __shfl_xor_sync(0xffffffffu, lm, o));

        float s = 0.f, a0 = 0.f, a1 = 0.f, a2 = 0.f;
        for (int j = lane; j < len; j += 32) {
            float e = __expf(sp[j] - lm);
            const float* vr = vp + (size_t)j * CV;
            s  += e;
            a0 = fmaf(e, vr[0], a0);
            a1 = fmaf(e, vr[1], a1);
            a2 = fmaf(e, vr[2], a2);
        }
        #pragma unroll
        for (int o = 16; o; o >>= 1) {
            s  += __shfl_xor_sync(0xffffffffu, s,  o);
            a0 += __shfl_xor_sync(0xffffffffu, a0, o);
            a1 += __shfl_xor_sync(0xffffffffu, a1, o);
            a2 += __shfl_xor_sync(0xffffffffu, a2, o);
        }
        const float inv = coef / s;
        res0 = fmaf(a0, inv, res0);
        res1 = fmaf(a1, inv, res1);
        res2 = fmaf(a2, inv, res2);
    }

    if (lane == 0) {
        float* o = out + ((size_t)p * HW + i) * CV;
        o[0] = res0; o[1] = res1; o[2] = res2;
    }
}

// ---------------------------------------------------------------------------
// Kernel 3: ground_truth copy
// ---------------------------------------------------------------------------
__global__ __launch_bounds__(256)
void copy_gt_kernel(const float* __restrict__ v, float* __restrict__ out)
{
    const int total = NPAIR * HW * CV;                 // 172032
    int idx = blockIdx.x * blockDim.x + threadIdx.x;
    if (idx < total) {
        const int per_b = 7 * HW * CV;                 // 21504
        const int b = idx / per_b;
        const int r = idx - b * per_b;
        out[(size_t)total + idx] = v[(size_t)b * (TT * HW * CV) + (HW * CV) + r];
    }
}

// ---------------------------------------------------------------------------
extern "C" void kernel_launch(void* const* d_in, const int* in_sizes, int n_in,
                              void* d_out, int out_size)
{
    const float* k   = (const float*)d_in[0];
    const float* v   = (const float*)d_in[1];
    const float* m_k = (const float*)d_in[2];
    const float* m_v = (const float*)d_in[3];
    float* out = (float*)d_out;

    (void)in_sizes; (void)n_in; (void)out_size;

    dim3 ggrid(NTOT / BN, HW / BM, NPAIR);     // (12, 8, 56)
    gemm_logits_kernel<<<ggrid, 256>>>(k, m_k);

    softmax_recon_kernel<<<(NPAIR * HW) / 8, 256>>>(v, m_v, out);

    const int total_gt = NPAIR * HW * CV;
    copy_gt_kernel<<<(total_gt + 255) / 256, 256>>>(v, out);
}

// round 5
// speedup vs baseline: 1.9309x; 1.2253x over previous
#include <cuda_runtime.h>
#include <cuda_bf16.h>
#include <math.h>
#include <stdint.h>

// Problem constants
#define BSZ   8
#define TT    8
#define HW    1024
#define CK    256
#define CV    3
#define MEM   512
#define NPAIR 56
#define NTOT  1536
#define COEF_MEM 0.2f

// Scratch (static device arrays; no allocs)
__device__ float g_S[(size_t)NPAIR * HW * NTOT];                    // 352 MB logits
__device__ __nv_bfloat16 g_khi[(size_t)BSZ * TT * HW * CK];
__device__ __nv_bfloat16 g_klo[(size_t)BSZ * TT * HW * CK];
__device__ __nv_bfloat16 g_mkhi[(size_t)BSZ * TT * MEM * CK];
__device__ __nv_bfloat16 g_mklo[(size_t)BSZ * TT * MEM * CK];

// ---------------------------------------------------------------------------
// Baseline-PTX helpers (sm_80+ portable: ldmatrix / mma.sync / cp.async)
// ---------------------------------------------------------------------------
__device__ __forceinline__ uint32_t smem_u32(const void* p) {
    uint32_t a;
    asm("{ .reg .u64 t; cvta.to.shared.u64 t, %1; cvt.u32.u64 %0, t; }"
        : "=r"(a) : "l"(p));
    return a;
}

#define CP_ASYNC16(dst, src) \
    asm volatile("cp.async.cg.shared.global [%0], [%1], 16;" \
                 :: "r"(dst), "l"(src))
#define CP_COMMIT() asm volatile("cp.async.commit_group;" ::: "memory")
#define CP_WAIT2()  asm volatile("cp.async.wait_group 2;" ::: "memory")

#define LDSM_X4(r0, r1, r2, r3, addr) \
    asm volatile("ldmatrix.sync.aligned.m8n8.x4.shared.b16 {%0,%1,%2,%3}, [%4];" \
                 : "=r"(r0), "=r"(r1), "=r"(r2), "=r"(r3) : "r"(addr))

#define MMA_BF16(d, a, b) \
    asm volatile("mma.sync.aligned.m16n8k16.row.col.f32.bf16.bf16.f32 " \
                 "{%0,%1,%2,%3}, {%4,%5,%6,%7}, {%8,%9}, {%0,%1,%2,%3};" \
                 : "+f"((d)[0]), "+f"((d)[1]), "+f"((d)[2]), "+f"((d)[3]) \
                 : "r"((a)[0]), "r"((a)[1]), "r"((a)[2]), "r"((a)[3]), \
                   "r"((b)[0]), "r"((b)[1]))

// ---------------------------------------------------------------------------
// Prep kernels: fp32 -> bf16 hi/lo split
// ---------------------------------------------------------------------------
__global__ __launch_bounds__(256)
void prep_k_kernel(const float* __restrict__ src)
{
    const int n4 = (BSZ * TT * HW * CK) / 4;
    int i = blockIdx.x * blockDim.x + threadIdx.x;
    if (i >= n4) return;
    float4 x = ((const float4*)src)[i];
    __nv_bfloat16 h0 = __float2bfloat16(x.x), h1 = __float2bfloat16(x.y);
    __nv_bfloat16 h2 = __float2bfloat16(x.z), h3 = __float2bfloat16(x.w);
    __nv_bfloat16 l0 = __float2bfloat16(x.x - __bfloat162float(h0));
    __nv_bfloat16 l1 = __float2bfloat16(x.y - __bfloat162float(h1));
    __nv_bfloat16 l2 = __float2bfloat16(x.z - __bfloat162float(h2));
    __nv_bfloat16 l3 = __float2bfloat16(x.w - __bfloat162float(h3));
    __nv_bfloat162* hp = (__nv_bfloat162*)g_khi;
    __nv_bfloat162* lp = (__nv_bfloat162*)g_klo;
    hp[2 * i] = {h0, h1}; hp[2 * i + 1] = {h2, h3};
    lp[2 * i] = {l0, l1}; lp[2 * i + 1] = {l2, l3};
}

__global__ __launch_bounds__(256)
void prep_mk_kernel(const float* __restrict__ src)
{
    const int n4 = (BSZ * TT * MEM * CK) / 4;
    int i = blockIdx.x * blockDim.x + threadIdx.x;
    if (i >= n4) return;
    float4 x = ((const float4*)src)[i];
    __nv_bfloat16 h0 = __float2bfloat16(x.x), h1 = __float2bfloat16(x.y);
    __nv_bfloat16 h2 = __float2bfloat16(x.z), h3 = __float2bfloat16(x.w);
    __nv_bfloat16 l0 = __float2bfloat16(x.x - __bfloat162float(h0));
    __nv_bfloat16 l1 = __float2bfloat16(x.y - __bfloat162float(h1));
    __nv_bfloat16 l2 = __float2bfloat16(x.z - __bfloat162float(h2));
    __nv_bfloat16 l3 = __float2bfloat16(x.w - __bfloat162float(h3));
    __nv_bfloat162* hp = (__nv_bfloat162*)g_mkhi;
    __nv_bfloat162* lp = (__nv_bfloat162*)g_mklo;
    hp[2 * i] = {h0, h1}; hp[2 * i + 1] = {h2, h3};
    lp[2 * i] = {l0, l1}; lp[2 * i + 1] = {l2, l3};
}

// ---------------------------------------------------------------------------
// Kernel 1: logits GEMM via mma.sync bf16, 3-term split.
// CTA: 128x128 tile. 8 warps (2x4), warp tile 64x32. BK=32, 3 cp.async stages.
// SMEM tile layout: 8x8-bf16-tile-major; tile (t8m, t8k) at offset
//   (t8m*4 + t8k)*128 + innerrow*16   (tile = 128 bytes contiguous)
// ---------------------------------------------------------------------------
#define STAGE_BYTES 32768           // 4 tiles x 8KB
#define GEMM_SMEM   (3 * STAGE_BYTES)

struct Srcs { const __nv_bfloat16 *aH, *aL, *bH, *bL; };

__device__ __forceinline__ void load_stage(uint32_t stage_base, const Srcs& S,
                                           int s, int tid)
{
    const int r = tid & 127;
    const int jbase = (tid >> 7) * 2;
    const size_t goff = (size_t)r * CK + (size_t)s * 32;
    const uint32_t dstrow = stage_base + (uint32_t)(((r >> 3) * 4) * 128 + (r & 7) * 16);
    const __nv_bfloat16* srcs[4] = {S.aH, S.aL, S.bH, S.bL};
    #pragma unroll
    for (int t4 = 0; t4 < 4; ++t4) {
        const __nv_bfloat16* g = srcs[t4] + goff;
        const uint32_t dstbase = dstrow + t4 * 8192;
        #pragma unroll
        for (int jj = 0; jj < 2; ++jj) {
            const int j = jbase + jj;
            CP_ASYNC16(dstbase + j * 128, g + j * 8);
        }
    }
}

__global__ __launch_bounds__(256)
void gemm_mma_kernel()
{
    extern __shared__ __align__(1024) char smem[];
    const uint32_t smem_base = smem_u32(smem);

    const int p  = blockIdx.z;
    const int bm = blockIdx.y;
    const int bn = blockIdx.x;
    const int b  = p / 7;
    const int t  = p % 7;
    const int tid  = threadIdx.x;
    const int wid  = tid >> 5;
    const int lane = tid & 31;
    const int wm = wid >> 2;            // 0..1 (64 rows)
    const int wn = wid & 3;             // 0..3 (32 cols)

    // Source pointers
    const size_t aoff = ((size_t)(b * TT + t + 1) * HW + (size_t)bm * 128) * CK;
    Srcs S;
    S.aH = g_khi + aoff;
    S.aL = g_klo + aoff;
    const int j0 = bn * 128;
    if (j0 < HW) {
        const size_t boff = ((size_t)(b * TT + t) * HW + (size_t)j0) * CK;
        S.bH = g_khi + boff; S.bL = g_klo + boff;
    } else {
        const size_t boff = ((size_t)(b * TT + t) * MEM + (size_t)(j0 - HW)) * CK;
        S.bH = g_mkhi + boff; S.bL = g_mklo + boff;
    }

    float acc[4][4][4];
    #pragma unroll
    for (int i = 0; i < 4; ++i)
        #pragma unroll
        for (int j = 0; j < 4; ++j)
            #pragma unroll
            for (int q = 0; q < 4; ++q) acc[i][j][q] = 0.f;

    // Prologue: 3 stages in flight
    load_stage(smem_base + 0 * STAGE_BYTES, S, 0, tid); CP_COMMIT();
    load_stage(smem_base + 1 * STAGE_BYTES, S, 1, tid); CP_COMMIT();
    load_stage(smem_base + 2 * STAGE_BYTES, S, 2, tid); CP_COMMIT();

    // ldmatrix lane geometry (same for A and B)
    const int grp_d0 = (lane >> 3) & 1;   // +1 within tile-pair (m or n)
    const int grp_dk = lane >> 4;         // +1 in k tile
    const int irow   = lane & 7;

    #pragma unroll 1
    for (int s = 0; s < 8; ++s) {
        CP_WAIT2();
        __syncthreads();

        const uint32_t sAh = smem_base + (uint32_t)(s % 3) * STAGE_BYTES;
        const uint32_t sAl = sAh + 8192;
        const uint32_t sBh = sAh + 16384;
        const uint32_t sBl = sAh + 24576;

        #pragma unroll
        for (int kk = 0; kk < 2; ++kk) {
            const int tk = kk * 2 + grp_dk;
            uint32_t ah[4][4], al[4][4], bhf[4][2], blf[4][2];

            #pragma unroll
            for (int mf = 0; mf < 4; ++mf) {
                const int tm = wm * 8 + mf * 2 + grp_d0;
                const uint32_t off = (uint32_t)((tm * 4 + tk) * 128 + irow * 16);
                LDSM_X4(ah[mf][0], ah[mf][1], ah[mf][2], ah[mf][3], sAh + off);
                LDSM_X4(al[mf][0], al[mf][1], al[mf][2], al[mf][3], sAl + off);
            }
            #pragma unroll
            for (int nf2 = 0; nf2 < 2; ++nf2) {
                const int tn = wn * 4 + nf2 * 2 + grp_d0;
                const uint32_t off = (uint32_t)((tn * 4 + tk) * 128 + irow * 16);
                uint32_t r0, r1, r2, r3;
                LDSM_X4(r0, r1, r2, r3, sBh + off);
                bhf[nf2 * 2][0] = r0;     bhf[nf2 * 2][1] = r2;
                bhf[nf2 * 2 + 1][0] = r1; bhf[nf2 * 2 + 1][1] = r3;
                LDSM_X4(r0, r1, r2, r3, sBl + off);
                blf[nf2 * 2][0] = r0;     blf[nf2 * 2][1] = r2;
                blf[nf2 * 2 + 1][0] = r1; blf[nf2 * 2 + 1][1] = r3;
            }

            #pragma unroll
            for (int mf = 0; mf < 4; ++mf)
                #pragma unroll
                for (int nf = 0; nf < 4; ++nf) {
                    MMA_BF16(acc[mf][nf], ah[mf], bhf[nf]);
                    MMA_BF16(acc[mf][nf], ah[mf], blf[nf]);
                    MMA_BF16(acc[mf][nf], al[mf], bhf[nf]);
                }
        }

        __syncthreads();
        if (s + 3 < 8)
            load_stage(smem_base + (uint32_t)((s + 3) % 3) * STAGE_BYTES, S, s + 3, tid);
        CP_COMMIT();
    }

    // Epilogue: fragment -> g_S
    const int g   = lane >> 2;
    const int tau = lane & 3;
    const size_t rowbase = (size_t)p * HW + (size_t)bm * 128 + wm * 64 + g;
    #pragma unroll
    for (int mf = 0; mf < 4; ++mf) {
        #pragma unroll
        for (int nf = 0; nf < 4; ++nf) {
            float* base = g_S + (rowbase + mf * 16) * NTOT
                        + j0 + wn * 32 + nf * 8 + tau * 2;
            float2 v0 = {acc[mf][nf][0], acc[mf][nf][1]};
            float2 v1 = {acc[mf][nf][2], acc[mf][nf][3]};
            *(float2*)base = v0;
            *(float2*)(base + 8 * NTOT) = v1;
        }
    }
}

// ---------------------------------------------------------------------------
// Kernel 2: warp-per-row dual softmax + reconstruction
// ---------------------------------------------------------------------------
__global__ __launch_bounds__(256)
void softmax_recon_kernel(const float* __restrict__ v,
                          const float* __restrict__ m_v,
                          float* __restrict__ out)
{
    const int lane = threadIdx.x & 31;
    const int row  = blockIdx.x * 8 + (threadIdx.x >> 5);
    const int p = row >> 10;
    const int i = row & 1023;
    const int b = p / 7;
    const int t = p % 7;

    const float* __restrict__ srow = g_S + ((size_t)p * HW + i) * NTOT;
    const float* __restrict__ vsrc  = v   + (size_t)(b * TT + t) * HW  * CV;
    const float* __restrict__ mvsrc = m_v + (size_t)(b * TT + t) * MEM * CV;

    float res0 = 0.f, res1 = 0.f, res2 = 0.f;

    #pragma unroll
    for (int seg = 0; seg < 2; ++seg) {
        const int   len  = seg ? MEM : HW;
        const float* sp  = srow + (seg ? HW : 0);
        const float* vp  = seg ? mvsrc : vsrc;
        const float coef = seg ? COEF_MEM : (1.0f - COEF_MEM);

        float lm = -INFINITY;
        for (int j = lane; j < len; j += 32) lm = fmaxf(lm, sp[j]);
        #pragma unroll
        for (int o = 16; o; o >>= 1)
            lm = fmaxf(lm, __shfl_xor_sync(0xffffffffu, lm, o));

        float s = 0.f, a0 = 0.f, a1 = 0.f, a2 = 0.f;
        for (int j = lane; j < len; j += 32) {
            float e = __expf(sp[j] - lm);
            const float* vr = vp + (size_t)j * CV;
            s  += e;
            a0 = fmaf(e, vr[0], a0);
            a1 = fmaf(e, vr[1], a1);
            a2 = fmaf(e, vr[2], a2);
        }
        #pragma unroll
        for (int o = 16; o; o >>= 1) {
            s  += __shfl_xor_sync(0xffffffffu, s,  o);
            a0 += __shfl_xor_sync(0xffffffffu, a0, o);
            a1 += __shfl_xor_sync(0xffffffffu, a1, o);
            a2 += __shfl_xor_sync(0xffffffffu, a2, o);
        }
        const float inv = coef / s;
        res0 = fmaf(a0, inv, res0);
        res1 = fmaf(a1, inv, res1);
        res2 = fmaf(a2, inv, res2);
    }

    if (lane == 0) {
        float* o = out + ((size_t)p * HW + i) * CV;
        o[0] = res0; o[1] = res1; o[2] = res2;
    }
}

// ---------------------------------------------------------------------------
// Kernel 3: ground_truth copy
// ---------------------------------------------------------------------------
__global__ __launch_bounds__(256)
void copy_gt_kernel(const float* __restrict__ v, float* __restrict__ out)
{
    const int total = NPAIR * HW * CV;
    int idx = blockIdx.x * blockDim.x + threadIdx.x;
    if (idx < total) {
        const int per_b = 7 * HW * CV;
        const int b = idx / per_b;
        const int r = idx - b * per_b;
        out[(size_t)total + idx] = v[(size_t)b * (TT * HW * CV) + (HW * CV) + r];
    }
}

// ---------------------------------------------------------------------------
extern "C" void kernel_launch(void* const* d_in, const int* in_sizes, int n_in,
                              void* d_out, int out_size)
{
    const float* k   = (const float*)d_in[0];
    const float* v   = (const float*)d_in[1];
    const float* m_k = (const float*)d_in[2];
    const float* m_v = (const float*)d_in[3];
    float* out = (float*)d_out;

    (void)in_sizes; (void)n_in; (void)out_size;

    cudaFuncSetAttribute(gemm_mma_kernel,
                         cudaFuncAttributeMaxDynamicSharedMemorySize, GEMM_SMEM);

    const int nk4  = (BSZ * TT * HW * CK) / 4;
    const int nmk4 = (BSZ * TT * MEM * CK) / 4;
    prep_k_kernel<<<(nk4 + 255) / 256, 256>>>(k);
    prep_mk_kernel<<<(nmk4 + 255) / 256, 256>>>(m_k);

    dim3 ggrid(NTOT / 128, HW / 128, NPAIR);   // (12, 8, 56)
    gemm_mma_kernel<<<ggrid, 256, GEMM_SMEM>>>();

    softmax_recon_kernel<<<(NPAIR * HW) / 8, 256>>>(v, m_v, out);

    const int total_gt = NPAIR * HW * CV;
    copy_gt_kernel<<<(total_gt + 255) / 256, 256>>>(v, out);
}

// round 6
// speedup vs baseline: 2.5908x; 1.3417x over previous
#include <cuda_runtime.h>
#include <cuda_bf16.h>
#include <math.h>
#include <stdint.h>

// Problem constants
#define BSZ   8
#define TT    8
#define HW    1024
#define CK    256
#define CV    3
#define MEM   512
#define NPAIR 56
#define NQ    (NPAIR * HW)     // 57344 queries total
#define COEF_MEM 0.2f

// Scratch (static device arrays; no allocs)
__device__ __nv_bfloat16 g_khi[(size_t)BSZ * TT * HW * CK];
__device__ __nv_bfloat16 g_klo[(size_t)BSZ * TT * HW * CK];
__device__ __nv_bfloat16 g_mkhi[(size_t)BSZ * TT * MEM * CK];
__device__ __nv_bfloat16 g_mklo[(size_t)BSZ * TT * MEM * CK];
// Partial softmax state: [split 0..2][query][8] = {m, s, a0, a1, a2, pad...}
__device__ float g_part[(size_t)3 * NQ * 8];

// ---------------------------------------------------------------------------
// Baseline-PTX helpers (sm_80+ portable)
// ---------------------------------------------------------------------------
__device__ __forceinline__ uint32_t smem_u32(const void* p) {
    uint32_t a;
    asm("{ .reg .u64 t; cvta.to.shared.u64 t, %1; cvt.u32.u64 %0, t; }"
        : "=r"(a) : "l"(p));
    return a;
}

#define CP_ASYNC16(dst, src) \
    asm volatile("cp.async.cg.shared.global [%0], [%1], 16;" \
                 :: "r"(dst), "l"(src))
#define CP_COMMIT() asm volatile("cp.async.commit_group;" ::: "memory")
#define CP_WAIT1()  asm volatile("cp.async.wait_group 1;" ::: "memory")

#define LDSM_X4(r0, r1, r2, r3, addr) \
    asm volatile("ldmatrix.sync.aligned.m8n8.x4.shared.b16 {%0,%1,%2,%3}, [%4];" \
                 : "=r"(r0), "=r"(r1), "=r"(r2), "=r"(r3) : "r"(addr))

#define MMA_BF16(d, a, b) \
    asm volatile("mma.sync.aligned.m16n8k16.row.col.f32.bf16.bf16.f32 " \
                 "{%0,%1,%2,%3}, {%4,%5,%6,%7}, {%8,%9}, {%0,%1,%2,%3};" \
                 : "+f"((d)[0]), "+f"((d)[1]), "+f"((d)[2]), "+f"((d)[3]) \
                 : "r"((a)[0]), "r"((a)[1]), "r"((a)[2]), "r"((a)[3]), \
                   "r"((b)[0]), "r"((b)[1]))

// ---------------------------------------------------------------------------
// Prep kernels: fp32 -> bf16 hi/lo split
// ---------------------------------------------------------------------------
__global__ __launch_bounds__(256)
void prep_k_kernel(const float* __restrict__ src)
{
    const int n4 = (BSZ * TT * HW * CK) / 4;
    int i = blockIdx.x * blockDim.x + threadIdx.x;
    if (i >= n4) return;
    float4 x = ((const float4*)src)[i];
    __nv_bfloat16 h0 = __float2bfloat16(x.x), h1 = __float2bfloat16(x.y);
    __nv_bfloat16 h2 = __float2bfloat16(x.z), h3 = __float2bfloat16(x.w);
    __nv_bfloat16 l0 = __float2bfloat16(x.x - __bfloat162float(h0));
    __nv_bfloat16 l1 = __float2bfloat16(x.y - __bfloat162float(h1));
    __nv_bfloat16 l2 = __float2bfloat16(x.z - __bfloat162float(h2));
    __nv_bfloat16 l3 = __float2bfloat16(x.w - __bfloat162float(h3));
    __nv_bfloat162* hp = (__nv_bfloat162*)g_khi;
    __nv_bfloat162* lp = (__nv_bfloat162*)g_klo;
    hp[2 * i] = {h0, h1}; hp[2 * i + 1] = {h2, h3};
    lp[2 * i] = {l0, l1}; lp[2 * i + 1] = {l2, l3};
}

__global__ __launch_bounds__(256)
void prep_mk_kernel(const float* __restrict__ src)
{
    const int n4 = (BSZ * TT * MEM * CK) / 4;
    int i = blockIdx.x * blockDim.x + threadIdx.x;
    if (i >= n4) return;
    float4 x = ((const float4*)src)[i];
    __nv_bfloat16 h0 = __float2bfloat16(x.x), h1 = __float2bfloat16(x.y);
    __nv_bfloat16 h2 = __float2bfloat16(x.z), h3 = __float2bfloat16(x.w);
    __nv_bfloat16 l0 = __float2bfloat16(x.x - __bfloat162float(h0));
    __nv_bfloat16 l1 = __float2bfloat16(x.y - __bfloat162float(h1));
    __nv_bfloat16 l2 = __float2bfloat16(x.z - __bfloat162float(h2));
    __nv_bfloat16 l3 = __float2bfloat16(x.w - __bfloat162float(h3));
    __nv_bfloat162* hp = (__nv_bfloat162*)g_mkhi;
    __nv_bfloat162* lp = (__nv_bfloat162*)g_mklo;
    hp[2 * i] = {h0, h1}; hp[2 * i + 1] = {h2, h3};
    lp[2 * i] = {l0, l1}; lp[2 * i + 1] = {l2, l3};
}

// ---------------------------------------------------------------------------
// Fused kernel: per CTA, 128 queries x 512 keys (one split).
//   split 0: keys   0..511 of k_flat[b,t]
//   split 1: keys 512..1023 of k_flat[b,t]
//   split 2: keys   0..511 of m_k[b,t]
// 4 chunks of 128 keys; per chunk: logits via 3-term bf16-split mma.sync,
// then chunk row-max exchange + online exp accumulation (per-lane partials).
// 8 warps = 4m x 2n, warp tile 32 rows x 64 cols.
// K streamed in 32-ck slices, triple-buffered cp.async. Q resident in SMEM.
// ---------------------------------------------------------------------------
#define SM_QHI 0
#define SM_QLO 65536
#define SM_K   131072               // 3 bufs x 16384 (hi 8KB + lo 8KB)
#define SM_V   180224               // 128 x float4 = 2048
#define SM_RED 182272               // 4KB: [parity][wn][128] floats
#define FUSED_SMEM 186368

__global__ __launch_bounds__(256)
void fused_attn_kernel(const float* __restrict__ v, const float* __restrict__ m_v)
{
    extern __shared__ __align__(1024) char smem[];
    const uint32_t sb = smem_u32(smem);

    const int bm = blockIdx.x;          // query block 0..7
    const int p  = blockIdx.y;          // pair 0..55
    const int sp = blockIdx.z;          // split 0..2
    const int b = p / 7, t = p % 7;
    const int tid = threadIdx.x, wid = tid >> 5, lane = tid & 31;
    const int wm = wid & 3;             // 4 m-warps, rows wm*32..+31
    const int wn = wid >> 2;            // 2 n-warps, cols wn*64..+63
    const int grp_d0 = (lane >> 3) & 1;
    const int grp_dk = lane >> 4;
    const int irow   = lane & 7;
    const int g   = lane >> 2;
    const int tau = lane & 3;

    // Source pointers
    const size_t qoff = ((size_t)(b * TT + t + 1) * HW + (size_t)bm * 128) * CK;
    const __nv_bfloat16* qhi = g_khi + qoff;
    const __nv_bfloat16* qlo = g_klo + qoff;
    const __nv_bfloat16 *khiP, *kloP;
    const float* vP;
    if (sp < 2) {
        const size_t ko = ((size_t)(b * TT + t) * HW + (size_t)sp * 512) * CK;
        khiP = g_khi + ko; kloP = g_klo + ko;
        vP = v + ((size_t)(b * TT + t) * HW + (size_t)sp * 512) * CV;
    } else {
        const size_t ko = (size_t)(b * TT + t) * MEM * CK;
        khiP = g_mkhi + ko; kloP = g_mklo + ko;
        vP = m_v + (size_t)(b * TT + t) * MEM * CV;
    }

    // --- Prologue: load Q (both splits) ---
    {
        const int r = tid >> 1;
        const int jb0 = (tid & 1) * 16;
        const uint32_t drow = sb + (uint32_t)(((r >> 3) * 32) * 128 + (r & 7) * 16);
        const size_t srow = (size_t)r * CK;
        #pragma unroll
        for (int jj = 0; jj < 16; ++jj) {
            const int jb = jb0 + jj;
            CP_ASYNC16(drow + SM_QHI + jb * 128, qhi + srow + jb * 8);
        }
        #pragma unroll
        for (int jj = 0; jj < 16; ++jj) {
            const int jb = jb0 + jj;
            CP_ASYNC16(drow + SM_QLO + jb * 128, qlo + srow + jb * 8);
        }
    }
    CP_COMMIT();

    // K slice loader: gs = chunk*8 + sl; slice = 128 keys x 32 ck, hi+lo.
    const int lr  = tid & 127;
    const int ljb = (tid >> 7) * 2;
    const uint32_t ldrow = (uint32_t)(((lr >> 3) * 4) * 128 + (lr & 7) * 16);

    #define LOAD_SLICE(gs_) do {                                               \
        const int c_ = (gs_) >> 3, sl_ = (gs_) & 7, q_ = (gs_) % 3;            \
        const uint32_t kb_ = sb + SM_K + (uint32_t)q_ * 16384 + ldrow;         \
        const size_t sr_ = (size_t)(c_ * 128 + lr) * CK + sl_ * 32;            \
        CP_ASYNC16(kb_ + (ljb + 0) * 128,        khiP + sr_ + (ljb + 0) * 8);  \
        CP_ASYNC16(kb_ + (ljb + 1) * 128,        khiP + sr_ + (ljb + 1) * 8);  \
        CP_ASYNC16(kb_ + 8192 + (ljb + 0) * 128, kloP + sr_ + (ljb + 0) * 8);  \
        CP_ASYNC16(kb_ + 8192 + (ljb + 1) * 128, kloP + sr_ + (ljb + 1) * 8);  \
    } while (0)

    LOAD_SLICE(0); CP_COMMIT();
    LOAD_SLICE(1); CP_COMMIT();

    float acc[2][8][4];
    float run_m[2][2], run_s[2][2], run_a[2][2][3];
    #pragma unroll
    for (int mt = 0; mt < 2; ++mt)
        #pragma unroll
        for (int h = 0; h < 2; ++h) {
            run_m[mt][h] = -INFINITY; run_s[mt][h] = 0.f;
            run_a[mt][h][0] = 0.f; run_a[mt][h][1] = 0.f; run_a[mt][h][2] = 0.f;
        }

    float* red = (float*)(smem + SM_RED);

    #pragma unroll 1
    for (int gs = 0; gs < 32; ++gs) {
        const int c = gs >> 3, sl = gs & 7, q = gs % 3;
        CP_WAIT1();
        __syncthreads();

        if (sl == 0) {
            if (tid < 128) {
                const float* vr = vP + (size_t)(c * 128 + tid) * CV;
                float4 vv; vv.x = vr[0]; vv.y = vr[1]; vv.z = vr[2]; vv.w = 0.f;
                *(float4*)(smem + SM_V + tid * 16) = vv;
            }
            #pragma unroll
            for (int mt = 0; mt < 2; ++mt)
                #pragma unroll
                for (int nt = 0; nt < 8; ++nt) {
                    acc[mt][nt][0] = 0.f; acc[mt][nt][1] = 0.f;
                    acc[mt][nt][2] = 0.f; acc[mt][nt][3] = 0.f;
                }
        }

        if (gs + 2 < 32) { LOAD_SLICE(gs + 2); }
        CP_COMMIT();

        const uint32_t kb = sb + SM_K + (uint32_t)q * 16384;
        #pragma unroll
        for (int kk = 0; kk < 2; ++kk) {
            uint32_t ah[2][4], al[2][4];
            const int t8k = sl * 4 + kk * 2 + grp_dk;
            #pragma unroll
            for (int mt = 0; mt < 2; ++mt) {
                const int tm8 = wm * 4 + mt * 2 + grp_d0;
                const uint32_t off = (uint32_t)((tm8 * 32 + t8k) * 128 + irow * 16);
                LDSM_X4(ah[mt][0], ah[mt][1], ah[mt][2], ah[mt][3], sb + SM_QHI + off);
                LDSM_X4(al[mt][0], al[mt][1], al[mt][2], al[mt][3], sb + SM_QLO + off);
            }
            uint32_t bh[8][2], bl[8][2];
            const int tk = kk * 2 + grp_dk;
            #pragma unroll
            for (int nf2 = 0; nf2 < 4; ++nf2) {
                const int tn = wn * 8 + nf2 * 2 + grp_d0;
                const uint32_t off = (uint32_t)((tn * 4 + tk) * 128 + irow * 16);
                uint32_t r0, r1, r2, r3;
                LDSM_X4(r0, r1, r2, r3, kb + off);
                bh[nf2 * 2][0] = r0;     bh[nf2 * 2][1] = r2;
                bh[nf2 * 2 + 1][0] = r1; bh[nf2 * 2 + 1][1] = r3;
                LDSM_X4(r0, r1, r2, r3, kb + 8192 + off);
                bl[nf2 * 2][0] = r0;     bl[nf2 * 2][1] = r2;
                bl[nf2 * 2 + 1][0] = r1; bl[nf2 * 2 + 1][1] = r3;
            }
            #pragma unroll
            for (int mt = 0; mt < 2; ++mt)
                #pragma unroll
                for (int nt = 0; nt < 8; ++nt) {
                    MMA_BF16(acc[mt][nt], ah[mt], bh[nt]);
                    MMA_BF16(acc[mt][nt], ah[mt], bl[nt]);
                    MMA_BF16(acc[mt][nt], al[mt], bh[nt]);
                }
        }

        if (sl == 7) {
            // ---- chunk epilogue: online softmax update ----
            const int cb = c & 1;
            float mx[2][2];
            #pragma unroll
            for (int mt = 0; mt < 2; ++mt)
                #pragma unroll
                for (int h = 0; h < 2; ++h) {
                    float m0 = -INFINITY;
                    #pragma unroll
                    for (int nt = 0; nt < 8; ++nt)
                        m0 = fmaxf(m0, fmaxf(acc[mt][nt][h * 2], acc[mt][nt][h * 2 + 1]));
                    m0 = fmaxf(m0, __shfl_xor_sync(0xffffffffu, m0, 1));
                    m0 = fmaxf(m0, __shfl_xor_sync(0xffffffffu, m0, 2));
                    mx[mt][h] = m0;
                }
            if (tau == 0) {
                #pragma unroll
                for (int mt = 0; mt < 2; ++mt)
                    #pragma unroll
                    for (int h = 0; h < 2; ++h) {
                        const int row = wm * 32 + mt * 16 + h * 8 + g;
                        red[cb * 256 + wn * 128 + row] = mx[mt][h];
                    }
            }
            __syncthreads();
            const float* vsm = (const float*)(smem + SM_V);
            #pragma unroll
            for (int mt = 0; mt < 2; ++mt)
                #pragma unroll
                for (int h = 0; h < 2; ++h) {
                    const int row = wm * 32 + mt * 16 + h * 8 + g;
                    const float cm = fmaxf(mx[mt][h], red[cb * 256 + (1 - wn) * 128 + row]);
                    const float nm = fmaxf(run_m[mt][h], cm);
                    const float alpha = __expf(run_m[mt][h] - nm);
                    run_m[mt][h] = nm;
                    float s  = run_s[mt][h] * alpha;
                    float a0 = run_a[mt][h][0] * alpha;
                    float a1 = run_a[mt][h][1] * alpha;
                    float a2 = run_a[mt][h][2] * alpha;
                    #pragma unroll
                    for (int nt = 0; nt < 8; ++nt) {
                        #pragma unroll
                        for (int cc = 0; cc < 2; ++cc) {
                            const float e = __expf(acc[mt][nt][h * 2 + cc] - nm);
                            const int col = wn * 64 + nt * 8 + tau * 2 + cc;
                            const float4 vv = *(const float4*)(vsm + col * 4);
                            s  += e;
                            a0 = fmaf(e, vv.x, a0);
                            a1 = fmaf(e, vv.y, a1);
                            a2 = fmaf(e, vv.z, a2);
                        }
                    }
                    run_s[mt][h] = s;
                    run_a[mt][h][0] = a0; run_a[mt][h][1] = a1; run_a[mt][h][2] = a2;
                }
        }
    }

    // ---- final: combine lane partials, then wn partials, write g_part ----
    #pragma unroll
    for (int mt = 0; mt < 2; ++mt)
        #pragma unroll
        for (int h = 0; h < 2; ++h) {
            #pragma unroll
            for (int o = 1; o <= 2; o <<= 1) {
                run_s[mt][h]    += __shfl_xor_sync(0xffffffffu, run_s[mt][h], o);
                run_a[mt][h][0] += __shfl_xor_sync(0xffffffffu, run_a[mt][h][0], o);
                run_a[mt][h][1] += __shfl_xor_sync(0xffffffffu, run_a[mt][h][1], o);
                run_a[mt][h][2] += __shfl_xor_sync(0xffffffffu, run_a[mt][h][2], o);
            }
        }
    __syncthreads();          // done with chunk-max buffer; reuse as float4[128]
    float4* red4 = (float4*)(smem + SM_RED);
    if (wn == 1 && tau == 0) {
        #pragma unroll
        for (int mt = 0; mt < 2; ++mt)
            #pragma unroll
            for (int h = 0; h < 2; ++h) {
                const int row = wm * 32 + mt * 16 + h * 8 + g;
                float4 w; w.x = run_s[mt][h];
                w.y = run_a[mt][h][0]; w.z = run_a[mt][h][1]; w.w = run_a[mt][h][2];
                red4[row] = w;
            }
    }
    __syncthreads();
    if (wn == 0 && tau == 0) {
        #pragma unroll
        for (int mt = 0; mt < 2; ++mt)
            #pragma unroll
            for (int h = 0; h < 2; ++h) {
                const int row = wm * 32 + mt * 16 + h * 8 + g;
                const float4 o = red4[row];
                float* dst = g_part + ((size_t)sp * NQ + (size_t)p * HW + bm * 128 + row) * 8;
                dst[0] = run_m[mt][h];
                dst[1] = run_s[mt][h] + o.x;
                dst[2] = run_a[mt][h][0] + o.y;
                dst[3] = run_a[mt][h][1] + o.z;
                dst[4] = run_a[mt][h][2] + o.w;
            }
    }
}

// ---------------------------------------------------------------------------
// Combine kernel: merge split 0+1 (k segment), add split 2 (memory segment)
// ---------------------------------------------------------------------------
__global__ __launch_bounds__(256)
void combine_kernel(float* __restrict__ out)
{
    const int qi = blockIdx.x * 256 + threadIdx.x;
    if (qi >= NQ) return;
    const float* p0 = g_part + ((size_t)0 * NQ + qi) * 8;
    const float* p1 = g_part + ((size_t)1 * NQ + qi) * 8;
    const float* p2 = g_part + ((size_t)2 * NQ + qi) * 8;
    const float M  = fmaxf(p0[0], p1[0]);
    const float w0 = __expf(p0[0] - M), w1 = __expf(p1[0] - M);
    const float Sk = p0[1] * w0 + p1[1] * w1;
    const float invk = (1.0f - COEF_MEM) / Sk;
    const float invm = COEF_MEM / p2[1];
    float* o = out + (size_t)qi * CV;
    o[0] = (p0[2] * w0 + p1[2] * w1) * invk + p2[2] * invm;
    o[1] = (p0[3] * w0 + p1[3] * w1) * invk + p2[3] * invm;
    o[2] = (p0[4] * w0 + p1[4] * w1) * invk + p2[4] * invm;
}

// ---------------------------------------------------------------------------
// Ground-truth copy
// ---------------------------------------------------------------------------
__global__ __launch_bounds__(256)
void copy_gt_kernel(const float* __restrict__ v, float* __restrict__ out)
{
    const int total = NQ * CV;
    int idx = blockIdx.x * blockDim.x + threadIdx.x;
    if (idx < total) {
        const int per_b = 7 * HW * CV;
        const int b = idx / per_b;
        const int r = idx - b * per_b;
        out[(size_t)total + idx] = v[(size_t)b * (TT * HW * CV) + (HW * CV) + r];
    }
}

// ---------------------------------------------------------------------------
extern "C" void kernel_launch(void* const* d_in, const int* in_sizes, int n_in,
                              void* d_out, int out_size)
{
    const float* k   = (const float*)d_in[0];
    const float* v   = (const float*)d_in[1];
    const float* m_k = (const float*)d_in[2];
    const float* m_v = (const float*)d_in[3];
    float* out = (float*)d_out;

    (void)in_sizes; (void)n_in; (void)out_size;

    cudaFuncSetAttribute(fused_attn_kernel,
                         cudaFuncAttributeMaxDynamicSharedMemorySize, FUSED_SMEM);

    const int nk4  = (BSZ * TT * HW * CK) / 4;
    const int nmk4 = (BSZ * TT * MEM * CK) / 4;
    prep_k_kernel<<<(nk4 + 255) / 256, 256>>>(k);
    prep_mk_kernel<<<(nmk4 + 255) / 256, 256>>>(m_k);

    dim3 fgrid(HW / 128, NPAIR, 3);            // (8, 56, 3) = 1344 CTAs
    fused_attn_kernel<<<fgrid, 256, FUSED_SMEM>>>(v, m_v);

    combine_kernel<<<(NQ + 255) / 256, 256>>>(out);

    const int total_gt = NQ * CV;
    copy_gt_kernel<<<(total_gt + 255) / 256, 256>>>(v, out);
}

// round 7
// speedup vs baseline: 2.6140x; 1.0090x over previous
#include <cuda_runtime.h>
#include <cuda_bf16.h>
#include <math.h>
#include <stdint.h>

// Problem constants
#define BSZ   8
#define TT    8
#define HW    1024
#define CK    256
#define CV    3
#define MEM   512
#define NPAIR 56
#define NQ    (NPAIR * HW)     // 57344 queries total
#define COEF_MEM 0.2f

// Scratch (static device arrays; no allocs)
__device__ __nv_bfloat16 g_khi[(size_t)BSZ * TT * HW * CK];
__device__ __nv_bfloat16 g_klo[(size_t)BSZ * TT * HW * CK];
__device__ __nv_bfloat16 g_mkhi[(size_t)BSZ * TT * MEM * CK];
__device__ __nv_bfloat16 g_mklo[(size_t)BSZ * TT * MEM * CK];
// Partial softmax state: [split 0..2][query][8] = {m, s, a0, a1, a2, pad}
__device__ float g_part[(size_t)3 * NQ * 8];

// ---------------------------------------------------------------------------
// Baseline-PTX helpers (sm_80+ portable)
// ---------------------------------------------------------------------------
__device__ __forceinline__ uint32_t smem_u32(const void* p) {
    uint32_t a;
    asm("{ .reg .u64 t; cvta.to.shared.u64 t, %1; cvt.u32.u64 %0, t; }"
        : "=r"(a) : "l"(p));
    return a;
}

#define CP_ASYNC16(dst, src) \
    asm volatile("cp.async.cg.shared.global [%0], [%1], 16;" \
                 :: "r"(dst), "l"(src))
#define CP_COMMIT() asm volatile("cp.async.commit_group;" ::: "memory")
#define CP_WAIT1()  asm volatile("cp.async.wait_group 1;" ::: "memory")

#define LDSM_X4(r0, r1, r2, r3, addr) \
    asm volatile("ldmatrix.sync.aligned.m8n8.x4.shared.b16 {%0,%1,%2,%3}, [%4];" \
                 : "=r"(r0), "=r"(r1), "=r"(r2), "=r"(r3) : "r"(addr))

#define MMA_BF16(d, a, b) \
    asm volatile("mma.sync.aligned.m16n8k16.row.col.f32.bf16.bf16.f32 " \
                 "{%0,%1,%2,%3}, {%4,%5,%6,%7}, {%8,%9}, {%0,%1,%2,%3};" \
                 : "+f"((d)[0]), "+f"((d)[1]), "+f"((d)[2]), "+f"((d)[3]) \
                 : "r"((a)[0]), "r"((a)[1]), "r"((a)[2]), "r"((a)[3]), \
                   "r"((b)[0]), "r"((b)[1]))

// ---------------------------------------------------------------------------
// Prep kernel (single launch): fp32 -> bf16 hi/lo split for k and m_k
// ---------------------------------------------------------------------------
#define NK4  ((BSZ * TT * HW * CK) / 4)
#define NMK4 ((BSZ * TT * MEM * CK) / 4)

__global__ __launch_bounds__(256)
void prep_kernel(const float* __restrict__ k, const float* __restrict__ m_k)
{
    int i = blockIdx.x * blockDim.x + threadIdx.x;
    const float* src;
    __nv_bfloat162 *hp, *lp;
    int idx;
    if (i < NK4) {
        src = k; idx = i;
        hp = (__nv_bfloat162*)g_khi; lp = (__nv_bfloat162*)g_klo;
    } else if (i < NK4 + NMK4) {
        src = m_k; idx = i - NK4;
        hp = (__nv_bfloat162*)g_mkhi; lp = (__nv_bfloat162*)g_mklo;
    } else {
        return;
    }
    float4 x = ((const float4*)src)[idx];
    __nv_bfloat16 h0 = __float2bfloat16(x.x), h1 = __float2bfloat16(x.y);
    __nv_bfloat16 h2 = __float2bfloat16(x.z), h3 = __float2bfloat16(x.w);
    __nv_bfloat16 l0 = __float2bfloat16(x.x - __bfloat162float(h0));
    __nv_bfloat16 l1 = __float2bfloat16(x.y - __bfloat162float(h1));
    __nv_bfloat16 l2 = __float2bfloat16(x.z - __bfloat162float(h2));
    __nv_bfloat16 l3 = __float2bfloat16(x.w - __bfloat162float(h3));
    hp[2 * idx] = {h0, h1}; hp[2 * idx + 1] = {h2, h3};
    lp[2 * idx] = {l0, l1}; lp[2 * idx + 1] = {l2, l3};
}

// ---------------------------------------------------------------------------
// Fused kernel: per CTA, 128 queries x 512 keys (one split).
//   split 0: keys   0..511 of k_flat[b,t]
//   split 1: keys 512..1023 of k_flat[b,t]
//   split 2: keys   0..511 of m_k[b,t]
// Per 128-key chunk: logits via 3-term bf16-split mma.sync, then PER-WARP
// online softmax (no cross-warp sync); wn halves merged once at the end.
// 8 warps = 4m x 2n, warp tile 32 rows x 64 cols.
// K streamed in 32-ck slices, triple-buffered cp.async. Q resident in SMEM.
// ---------------------------------------------------------------------------
#define SM_QHI 0
#define SM_QLO 65536
#define SM_K   131072               // 3 bufs x 16384 (hi 8KB + lo 8KB)
#define SM_V   180224               // 128 x float4 = 2048
#define SM_RED 182272               // 4KB: [128][8] floats for final merge
#define FUSED_SMEM 186368

__global__ __launch_bounds__(256)
void fused_attn_kernel(const float* __restrict__ v, const float* __restrict__ m_v)
{
    extern __shared__ __align__(1024) char smem[];
    const uint32_t sb = smem_u32(smem);

    const int bm = blockIdx.x;          // query block 0..7
    const int p  = blockIdx.y;          // pair 0..55
    const int sp = blockIdx.z;          // split 0..2
    const int b = p / 7, t = p % 7;
    const int tid = threadIdx.x, wid = tid >> 5, lane = tid & 31;
    const int wm = wid & 3;             // 4 m-warps, rows wm*32..+31
    const int wn = wid >> 2;            // 2 n-warps, cols wn*64..+63
    const int grp_d0 = (lane >> 3) & 1;
    const int grp_dk = lane >> 4;
    const int irow   = lane & 7;
    const int g   = lane >> 2;
    const int tau = lane & 3;

    // Source pointers
    const size_t qoff = ((size_t)(b * TT + t + 1) * HW + (size_t)bm * 128) * CK;
    const __nv_bfloat16* qhi = g_khi + qoff;
    const __nv_bfloat16* qlo = g_klo + qoff;
    const __nv_bfloat16 *khiP, *kloP;
    const float* vP;
    if (sp < 2) {
        const size_t ko = ((size_t)(b * TT + t) * HW + (size_t)sp * 512) * CK;
        khiP = g_khi + ko; kloP = g_klo + ko;
        vP = v + ((size_t)(b * TT + t) * HW + (size_t)sp * 512) * CV;
    } else {
        const size_t ko = (size_t)(b * TT + t) * MEM * CK;
        khiP = g_mkhi + ko; kloP = g_mklo + ko;
        vP = m_v + (size_t)(b * TT + t) * MEM * CV;
    }

    // --- Prologue: load Q (hi + lo) ---
    {
        const int r = tid >> 1;
        const int jb0 = (tid & 1) * 16;
        const uint32_t drow = sb + (uint32_t)(((r >> 3) * 32) * 128 + (r & 7) * 16);
        const size_t srow = (size_t)r * CK;
        #pragma unroll
        for (int jj = 0; jj < 16; ++jj) {
            const int jb = jb0 + jj;
            CP_ASYNC16(drow + SM_QHI + jb * 128, qhi + srow + jb * 8);
        }
        #pragma unroll
        for (int jj = 0; jj < 16; ++jj) {
            const int jb = jb0 + jj;
            CP_ASYNC16(drow + SM_QLO + jb * 128, qlo + srow + jb * 8);
        }
    }
    CP_COMMIT();

    // K slice loader: gs = chunk*8 + sl; slice = 128 keys x 32 ck, hi+lo.
    const int lr  = tid & 127;
    const int ljb = (tid >> 7) * 2;
    const uint32_t ldrow = (uint32_t)(((lr >> 3) * 4) * 128 + (lr & 7) * 16);

    #define LOAD_SLICE(gs_) do {                                               \
        const int c_ = (gs_) >> 3, sl_ = (gs_) & 7, q_ = (gs_) % 3;            \
        const uint32_t kb_ = sb + SM_K + (uint32_t)q_ * 16384 + ldrow;         \
        const size_t sr_ = (size_t)(c_ * 128 + lr) * CK + sl_ * 32;            \
        CP_ASYNC16(kb_ + (ljb + 0) * 128,        khiP + sr_ + (ljb + 0) * 8);  \
        CP_ASYNC16(kb_ + (ljb + 1) * 128,        khiP + sr_ + (ljb + 1) * 8);  \
        CP_ASYNC16(kb_ + 8192 + (ljb + 0) * 128, kloP + sr_ + (ljb + 0) * 8);  \
        CP_ASYNC16(kb_ + 8192 + (ljb + 1) * 128, kloP + sr_ + (ljb + 1) * 8);  \
    } while (0)

    LOAD_SLICE(0); CP_COMMIT();
    LOAD_SLICE(1); CP_COMMIT();

    float acc[2][8][4];
    float run_m[2][2], run_s[2][2], run_a[2][2][3];
    #pragma unroll
    for (int mt = 0; mt < 2; ++mt)
        #pragma unroll
        for (int h = 0; h < 2; ++h) {
            run_m[mt][h] = -INFINITY; run_s[mt][h] = 0.f;
            run_a[mt][h][0] = 0.f; run_a[mt][h][1] = 0.f; run_a[mt][h][2] = 0.f;
        }

    #pragma unroll 1
    for (int gs = 0; gs < 32; ++gs) {
        const int c = gs >> 3, sl = gs & 7, q = gs % 3;
        CP_WAIT1();
        __syncthreads();

        if (sl == 0) {
            if (tid < 128) {
                const float* vr = vP + (size_t)(c * 128 + tid) * CV;
                float4 vv; vv.x = vr[0]; vv.y = vr[1]; vv.z = vr[2]; vv.w = 0.f;
                *(float4*)(smem + SM_V + tid * 16) = vv;
            }
            #pragma unroll
            for (int mt = 0; mt < 2; ++mt)
                #pragma unroll
                for (int nt = 0; nt < 8; ++nt) {
                    acc[mt][nt][0] = 0.f; acc[mt][nt][1] = 0.f;
                    acc[mt][nt][2] = 0.f; acc[mt][nt][3] = 0.f;
                }
        }

        if (gs + 2 < 32) { LOAD_SLICE(gs + 2); }
        CP_COMMIT();

        const uint32_t kb = sb + SM_K + (uint32_t)q * 16384;
        #pragma unroll
        for (int kk = 0; kk < 2; ++kk) {
            uint32_t ah[2][4], al[2][4];
            const int t8k = sl * 4 + kk * 2 + grp_dk;
            #pragma unroll
            for (int mt = 0; mt < 2; ++mt) {
                const int tm8 = wm * 4 + mt * 2 + grp_d0;
                const uint32_t off = (uint32_t)((tm8 * 32 + t8k) * 128 + irow * 16);
                LDSM_X4(ah[mt][0], ah[mt][1], ah[mt][2], ah[mt][3], sb + SM_QHI + off);
                LDSM_X4(al[mt][0], al[mt][1], al[mt][2], al[mt][3], sb + SM_QLO + off);
            }
            uint32_t bh[8][2], bl[8][2];
            const int tk = kk * 2 + grp_dk;
            #pragma unroll
            for (int nf2 = 0; nf2 < 4; ++nf2) {
                const int tn = wn * 8 + nf2 * 2 + grp_d0;
                const uint32_t off = (uint32_t)((tn * 4 + tk) * 128 + irow * 16);
                uint32_t r0, r1, r2, r3;
                LDSM_X4(r0, r1, r2, r3, kb + off);
                bh[nf2 * 2][0] = r0;     bh[nf2 * 2][1] = r2;
                bh[nf2 * 2 + 1][0] = r1; bh[nf2 * 2 + 1][1] = r3;
                LDSM_X4(r0, r1, r2, r3, kb + 8192 + off);
                bl[nf2 * 2][0] = r0;     bl[nf2 * 2][1] = r2;
                bl[nf2 * 2 + 1][0] = r1; bl[nf2 * 2 + 1][1] = r3;
            }
            #pragma unroll
            for (int mt = 0; mt < 2; ++mt)
                #pragma unroll
                for (int nt = 0; nt < 8; ++nt) {
                    MMA_BF16(acc[mt][nt], ah[mt], bh[nt]);
                    MMA_BF16(acc[mt][nt], ah[mt], bl[nt]);
                    MMA_BF16(acc[mt][nt], al[mt], bh[nt]);
                }
        }

        if (sl == 7) {
            // ---- chunk epilogue: PER-WARP online softmax (no block sync) ----
            float nm[2][2];
            #pragma unroll
            for (int mt = 0; mt < 2; ++mt)
                #pragma unroll
                for (int h = 0; h < 2; ++h) {
                    float m0 = -INFINITY;
                    #pragma unroll
                    for (int nt = 0; nt < 8; ++nt)
                        m0 = fmaxf(m0, fmaxf(acc[mt][nt][h * 2], acc[mt][nt][h * 2 + 1]));
                    m0 = fmaxf(m0, __shfl_xor_sync(0xffffffffu, m0, 1));
                    m0 = fmaxf(m0, __shfl_xor_sync(0xffffffffu, m0, 2));
                    const float n = fmaxf(run_m[mt][h], m0);
                    const float alpha = __expf(run_m[mt][h] - n);
                    run_m[mt][h] = n;
                    nm[mt][h] = n;
                    run_s[mt][h]    *= alpha;
                    run_a[mt][h][0] *= alpha;
                    run_a[mt][h][1] *= alpha;
                    run_a[mt][h][2] *= alpha;
                }
            const float* vsm = (const float*)(smem + SM_V);
            #pragma unroll
            for (int nt = 0; nt < 8; ++nt) {
                #pragma unroll
                for (int cc = 0; cc < 2; ++cc) {
                    const int col = wn * 64 + nt * 8 + tau * 2 + cc;
                    const float4 vv = *(const float4*)(vsm + col * 4);
                    #pragma unroll
                    for (int mt = 0; mt < 2; ++mt)
                        #pragma unroll
                        for (int h = 0; h < 2; ++h) {
                            const float e = __expf(acc[mt][nt][h * 2 + cc] - nm[mt][h]);
                            run_s[mt][h] += e;
                            run_a[mt][h][0] = fmaf(e, vv.x, run_a[mt][h][0]);
                            run_a[mt][h][1] = fmaf(e, vv.y, run_a[mt][h][1]);
                            run_a[mt][h][2] = fmaf(e, vv.z, run_a[mt][h][2]);
                        }
                }
            }
        }
    }

    // ---- final: quad-reduce lane partials, merge the two wn halves ----
    #pragma unroll
    for (int mt = 0; mt < 2; ++mt)
        #pragma unroll
        for (int h = 0; h < 2; ++h) {
            #pragma unroll
            for (int o = 1; o <= 2; o <<= 1) {
                run_s[mt][h]    += __shfl_xor_sync(0xffffffffu, run_s[mt][h], o);
                run_a[mt][h][0] += __shfl_xor_sync(0xffffffffu, run_a[mt][h][0], o);
                run_a[mt][h][1] += __shfl_xor_sync(0xffffffffu, run_a[mt][h][1], o);
                run_a[mt][h][2] += __shfl_xor_sync(0xffffffffu, run_a[mt][h][2], o);
            }
        }
    __syncthreads();
    float* red = (float*)(smem + SM_RED);       // [128][8]
    if (wn == 1 && tau == 0) {
        #pragma unroll
        for (int mt = 0; mt < 2; ++mt)
            #pragma unroll
            for (int h = 0; h < 2; ++h) {
                const int row = wm * 32 + mt * 16 + h * 8 + g;
                float* w = red + row * 8;
                w[0] = run_m[mt][h];
                w[1] = run_s[mt][h];
                w[2] = run_a[mt][h][0];
                w[3] = run_a[mt][h][1];
                w[4] = run_a[mt][h][2];
            }
    }
    __syncthreads();
    if (wn == 0 && tau == 0) {
        #pragma unroll
        for (int mt = 0; mt < 2; ++mt)
            #pragma unroll
            for (int h = 0; h < 2; ++h) {
                const int row = wm * 32 + mt * 16 + h * 8 + g;
                const float* w = red + row * 8;
                const float M  = fmaxf(run_m[mt][h], w[0]);
                const float e0 = __expf(run_m[mt][h] - M);
                const float e1 = __expf(w[0] - M);
                float* dst = g_part + ((size_t)sp * NQ + (size_t)p * HW + bm * 128 + row) * 8;
                dst[0] = M;
                dst[1] = run_s[mt][h] * e0 + w[1] * e1;
                dst[2] = run_a[mt][h][0] * e0 + w[2] * e1;
                dst[3] = run_a[mt][h][1] * e0 + w[3] * e1;
                dst[4] = run_a[mt][h][2] * e0 + w[4] * e1;
            }
    }
}

// ---------------------------------------------------------------------------
// Finish kernel: combine splits (first NQ threads) + ground-truth copy
// ---------------------------------------------------------------------------
__global__ __launch_bounds__(256)
void finish_kernel(const float* __restrict__ v, float* __restrict__ out)
{
    const int idx = blockIdx.x * 256 + threadIdx.x;
    const int total = NQ * CV;
    if (idx < total) {
        const int per_b = 7 * HW * CV;
        const int b = idx / per_b;
        const int r = idx - b * per_b;
        out[(size_t)total + idx] = v[(size_t)b * (TT * HW * CV) + (HW * CV) + r];
    }
    if (idx < NQ) {
        const float* p0 = g_part + ((size_t)0 * NQ + idx) * 8;
        const float* p1 = g_part + ((size_t)1 * NQ + idx) * 8;
        const float* p2 = g_part + ((size_t)2 * NQ + idx) * 8;
        const float M  = fmaxf(p0[0], p1[0]);
        const float w0 = __expf(p0[0] - M), w1 = __expf(p1[0] - M);
        const float Sk = p0[1] * w0 + p1[1] * w1;
        const float invk = (1.0f - COEF_MEM) / Sk;
        const float invm = COEF_MEM / p2[1];
        float* o = out + (size_t)idx * CV;
        o[0] = (p0[2] * w0 + p1[2] * w1) * invk + p2[2] * invm;
        o[1] = (p0[3] * w0 + p1[3] * w1) * invk + p2[3] * invm;
        o[2] = (p0[4] * w0 + p1[4] * w1) * invk + p2[4] * invm;
    }
}

// ---------------------------------------------------------------------------
extern "C" void kernel_launch(void* const* d_in, const int* in_sizes, int n_in,
                              void* d_out, int out_size)
{
    const float* k   = (const float*)d_in[0];
    const float* v   = (const float*)d_in[1];
    const float* m_k = (const float*)d_in[2];
    const float* m_v = (const float*)d_in[3];
    float* out = (float*)d_out;

    (void)in_sizes; (void)n_in; (void)out_size;

    cudaFuncSetAttribute(fused_attn_kernel,
                         cudaFuncAttributeMaxDynamicSharedMemorySize, FUSED_SMEM);

    prep_kernel<<<(NK4 + NMK4 + 255) / 256, 256>>>(k, m_k);

    dim3 fgrid(HW / 128, NPAIR, 3);            // (8, 56, 3) = 1344 CTAs
    fused_attn_kernel<<<fgrid, 256, FUSED_SMEM>>>(v, m_v);

    finish_kernel<<<(NQ * CV + 255) / 256, 256>>>(v, out);
}